// round 17
// baseline (speedup 1.0000x reference)
#include <cuda_runtime.h>

typedef unsigned long long ull;

__device__ __forceinline__ ull pack2(float lo, float hi) {
    ull r; asm("mov.b64 %0, {%1, %2};" : "=l"(r) : "f"(lo), "f"(hi)); return r;
}
__device__ __forceinline__ void unpack2(ull v, float& lo, float& hi) {
    asm("mov.b64 {%0, %1}, %2;" : "=f"(lo), "=f"(hi) : "l"(v));
}
__device__ __forceinline__ void fma2(ull& d, ull a, ull b) {
    asm("fma.rn.f32x2 %0, %1, %2, %0;" : "+l"(d) : "l"(a), "l"(b));
}
__device__ __forceinline__ float ex2f(float x) {
    float y; asm("ex2.approx.f32 %0, %1;" : "=f"(y) : "f"(x)); return y;
}

// ---------------- scratch (no allocations allowed) ----------------
#define NTOK (2*4096)              // 8192 tokens
#define PBUF (NTOK*64)             // 524288 floats per partial buffer
__device__ float g_p[4*PBUF];      // conv1 partials (per ci-quarter)
__device__ float g_q[4*PBUF];      // conv2 partials (per ci-quarter)
__device__ float g_wt1[64*9*64];   // [ci][k][(co2,s)]: pair = (co2, co2+32)
__device__ float g_wt2[64*9*64];

// ---- prep: [co][ci][3][3] -> [ci][k][(co2,s)] where pair = (co2, co2+32) ----
__global__ void k_transpose_w(const float* __restrict__ w1, const float* __restrict__ w2) {
    int i = blockIdx.x * blockDim.x + threadIdx.x;
    if (i >= 2 * 36864) return;
    const float* w = (i < 36864) ? w1 : w2;
    float* dst     = (i < 36864) ? g_wt1 : g_wt2;
    int o   = (i < 36864) ? i : (i - 36864);
    int ci  = o / 576;
    int rem = o - ci * 576;
    int kk  = rem >> 6;
    int qq  = rem & 63;
    int co2 = qq >> 1;
    int s   = qq & 1;
    dst[o] = w[(s * 32 + co2) * 576 + ci * 9 + kk];
}

// ---------------- partial conv3x3: 16 ci x 64 co, tile 2 rows x 64 px (R16) --------
#define IN_CI_STRIDE 276   // 4 rows * 68 + pad; 16B-aligned, %32 = 20 (conflict-free)
template<int SRC>
__global__ void __launch_bounds__(512, 2) k_conv(const float* __restrict__ in_x,
                                                 const float* __restrict__ in_bias) {
    const float* __restrict__ wt = (SRC == 0) ? g_wt1 : g_wt2;

    __shared__ float w_s[16 * 576];              // 36.9 KB
    __shared__ float in_s[16 * IN_CI_STRIDE];    // 17.7 KB; [ci][r*68 + xx], r<4, xx<66

    const int tid = threadIdx.x;
    const int co2 = tid & 31;
    const int h   = (tid >> 5) & 7;              // 8-px group, uniform per warp
    const int rg  = tid >> 8;                    // output row 0/1, uniform per warp
    const int y0 = blockIdx.y * 2;
    const int b       = blockIdx.z >> 2;
    const int quarter = blockIdx.z & 3;

    {
        const float2* wsrc = (const float2*)(wt + quarter * 16 * 576);
        float2* wdst = (float2*)w_s;
#pragma unroll
        for (int i = 0; i < 9; i++)
            wdst[tid + i * 512] = wsrc[tid + i * 512];
    }
    if (SRC == 0) {
#pragma unroll
        for (int i = 0; i < 9; i++) {
            int e = i * 512 + tid;
            if (e < 4224) {
                int xx = e % 66;
                int t  = e / 66;
                int r  = t & 3;
                int ci = t >> 2;
                int y  = y0 - 1 + r;
                int xg = xx - 1;
                float v = 0.f;
                if ((unsigned)y < 64u && (unsigned)xg < 64u)
                    v = in_x[((b * 64 + quarter * 16 + ci) * 64 + y) * 64 + xg];
                in_s[ci * IN_CI_STRIDE + r * 68 + xx] = v;
            }
        }
    } else {
        const int ci = tid & 15;
        const float bvin = in_bias[quarter * 16 + ci];
#pragma unroll
        for (int i = 0; i < 9; i++) {
            int e = i * 512 + tid;
            if (e < 4224) {
                int t  = e >> 4;
                int r  = t / 66;
                int xx = t - r * 66;
                int y  = y0 - 1 + r;
                int xg = xx - 1;
                float v = 0.f;
                if ((unsigned)y < 64u && (unsigned)xg < 64u) {
                    int idx = ((b * 64 + y) * 64 + xg) * 64 + quarter * 16 + ci;
                    float s0 = g_p[idx]          + g_p[idx + PBUF];
                    float s1 = g_p[idx + 2*PBUF] + g_p[idx + 3*PBUF];
                    v = fmaxf(s0 + s1 + bvin, 0.f);
                }
                in_s[ci * IN_CI_STRIDE + r * 68 + xx] = v;
            }
        }
    }
    __syncthreads();

    ull acc[8] = {0,0,0,0,0,0,0,0};

#pragma unroll 4
    for (int ci = 0; ci < 16; ci++) {
        const ull* wp = (const ull*)(w_s + ci * 576) + co2;
        ull w2[9];
#pragma unroll
        for (int k = 0; k < 9; k++) w2[k] = wp[k * 32];

        const float* ibase = in_s + ci * IN_CI_STRIDE + rg * 68 + h * 8;
#pragma unroll
        for (int dy = 0; dy < 3; dy++) {
            const float* row = ibase + dy * 68;
            {
                float4 v0 = *(const float4*)(row);
                float2 v1 = *(const float2*)(row + 4);
                ull d[6];
                d[0] = pack2(v0.x, v0.x); d[1] = pack2(v0.y, v0.y);
                d[2] = pack2(v0.z, v0.z); d[3] = pack2(v0.w, v0.w);
                d[4] = pack2(v1.x, v1.x); d[5] = pack2(v1.y, v1.y);
#pragma unroll
                for (int p = 0; p < 4; p++) {
                    fma2(acc[p], w2[dy*3+0], d[p]);
                    fma2(acc[p], w2[dy*3+1], d[p+1]);
                    fma2(acc[p], w2[dy*3+2], d[p+2]);
                }
            }
            {
                float2 v0 = *(const float2*)(row + 4);
                float4 v1 = *(const float4*)(row + 6);
                ull d[6];
                d[0] = pack2(v0.x, v0.x); d[1] = pack2(v0.y, v0.y);
                d[2] = pack2(v1.x, v1.x); d[3] = pack2(v1.y, v1.y);
                d[4] = pack2(v1.z, v1.z); d[5] = pack2(v1.w, v1.w);
#pragma unroll
                for (int p = 0; p < 4; p++) {
                    fma2(acc[4+p], w2[dy*3+0], d[p]);
                    fma2(acc[4+p], w2[dy*3+1], d[p+1]);
                    fma2(acc[4+p], w2[dy*3+2], d[p+2]);
                }
            }
        }
    }

    float* __restrict__ out = ((SRC == 0) ? g_p : g_q) + quarter * PBUF;
    int y = y0 + rg;
    int base = ((b * 64 + y) * 64 + h * 8) * 64;
#pragma unroll
    for (int p = 0; p < 8; p++) {
        float lo, hi;
        unpack2(acc[p], lo, hi);
        out[base + p * 64 + co2]      = lo;
        out[base + p * 64 + co2 + 32] = hi;
    }
}

// ---------------- attention: 32 tokens/block, 512 threads ----------------
// mapping: tt = tid & 31 (token = lane), cg = tid >> 5 (warp, 0..15), 4 ch/thread.
#define OFF_WQ 0
#define OFF_WK 4224
#define OFF_WV 8448
#define OFF_WO 12672
#define OFF_T   16896              // [32][65]
#define OFF_KV  18976              // float2 [32][65]
#define OFF_O2T 23136              // float2 [64][33]: o2t[c][tt] = {o,o} (dup, transposed)
#define OFF_SQ  27360              // [16][33]
#define OFF_SK  27888
#define SMEM_FLOATS 28416          // 113664 bytes -> 2 blocks/SM

__global__ void __launch_bounds__(512) k_attn(
    const float* __restrict__ wq, const float* __restrict__ wk,
    const float* __restrict__ wv, const float* __restrict__ wo,
    const float* __restrict__ bo, const float* __restrict__ b2,
    float* __restrict__ out)
{
    extern __shared__ float sm[];
    float*  wq_s  = sm + OFF_WQ;   // [l][c], stride 66
    float*  wk_s  = sm + OFF_WK;
    float*  wv_s  = sm + OFF_WV;
    float*  wo_s  = sm + OFF_WO;
    float*  t_s   = sm + OFF_T;
    float2* kv_s  = (float2*)(sm + OFF_KV);
    float2* o2t_s = (float2*)(sm + OFF_O2T);   // [c][tt] duplicated pairs
    float*  sq_s  = sm + OFF_SQ;
    float*  sk_s  = sm + OFF_SK;

    int tid = threadIdx.x;
    int n0  = blockIdx.x * 32;

#pragma unroll
    for (int i = 0; i < 8; i++) {
        int gg = tid + i * 512;
        int c = gg >> 6, l = gg & 63;
        wq_s[l * 66 + c] = wq[gg];
        wk_s[l * 66 + c] = wk[gg];
        wv_s[l * 66 + c] = wv[gg];
        wo_s[l * 66 + c] = wo[gg];
    }
#pragma unroll
    for (int i = 0; i < 4; i++) {
        int gg = tid + i * 512;
        int idx = n0 * 64 + gg;
        float s0 = g_q[idx]          + g_q[idx + PBUF];
        float s1 = g_q[idx + 2*PBUF] + g_q[idx + 3*PBUF];
        t_s[(gg >> 6) * 65 + (gg & 63)] = s0 + s1 + b2[gg & 63];
    }
    __syncthreads();                                   // B1

    const int tt = tid & 31;
    const int cg = tid >> 5;       // 0..15 (uniform per warp)
    const int c0 = cg * 4;

    // phase 1: q/k/v matvecs (4 channels each, fma2 + LDS.128)
    ull q2[2] = {0,0}, k2[2] = {0,0}, v2[2] = {0,0};
    const float* trow = t_s + tt * 65;
#pragma unroll 4
    for (int l = 0; l < 64; l++) {
        float tl = trow[l];
        ull tl2 = pack2(tl, tl);
        const ull* wql = (const ull*)(wq_s + l * 66 + c0);
        const ull* wkl = (const ull*)(wk_s + l * 66 + c0);
        const ull* wvl = (const ull*)(wv_s + l * 66 + c0);
        fma2(q2[0], tl2, wql[0]); fma2(q2[1], tl2, wql[1]);
        fma2(k2[0], tl2, wkl[0]); fma2(k2[1], tl2, wkl[1]);
        fma2(v2[0], tl2, wvl[0]); fma2(v2[1], tl2, wvl[1]);
    }
    float q[4], kk[4], vv[4];
    unpack2(q2[0], q[0], q[1]);  unpack2(q2[1], q[2], q[3]);
    unpack2(k2[0], kk[0], kk[1]); unpack2(k2[1], kk[2], kk[3]);
    unpack2(v2[0], vv[0], vv[1]); unpack2(v2[1], vv[2], vv[3]);

    float sq = 0.f, sk = 0.f;
#pragma unroll
    for (int j = 0; j < 4; j++) { sq = fmaf(q[j], q[j], sq); sk = fmaf(kk[j], kk[j], sk); }
    sq_s[cg * 33 + tt] = sq;
    sk_s[cg * 33 + tt] = sk;
#pragma unroll
    for (int j = 0; j < 4; j++)
        kv_s[tt * 65 + c0 + j] = make_float2(kk[j], vv[j]);   // raw k,v
    __syncthreads();                                   // B2

    sq = 0.f; sk = 0.f;
#pragma unroll
    for (int m = 0; m < 16; m++) { sq += sq_s[m * 33 + tt]; sk += sk_s[m * 33 + tt]; }
    const float LOG2E = 1.4426950408889634f;
    // fold invq * invk * log2(e) into q; k stays raw in smem
    float scale = __fdividef(LOG2E,
                             fmaxf(sqrtf(sq), 1e-12f) * fmaxf(sqrtf(sk), 1e-12f));
    float qs[4];
#pragma unroll
    for (int j = 0; j < 4; j++) qs[j] = q[j] * scale;

    // phase 2: rank-1 softmax, all-scalar (no packing in the MUFU loop)
    float num[4] = {0.f, 0.f, 0.f, 0.f};
    float den[4] = {0.f, 0.f, 0.f, 0.f};
    const float2* kvrow = kv_s + tt * 65;
#pragma unroll 4
    for (int d = 0; d < 64; d++) {
        float2 kv = kvrow[d];
#pragma unroll
        for (int j = 0; j < 4; j++) {
            float e = ex2f(qs[j] * kv.x);
            num[j] = fmaf(e, kv.y, num[j]);
            den[j] += e;
        }
    }
    // write duplicated+transposed o: o2t[c][tt] = {o, o} (conflict-free STS.64)
#pragma unroll
    for (int j = 0; j < 4; j++) {
        float o = __fdividef(num[j], den[j]);
        o2t_s[(c0 + j) * 33 + tt] = make_float2(o, o);
    }
    __syncthreads();                                   // B3

    // phase 3: Wo projection; o pairs read directly (no packing)
    ull fin2[2] = {0,0};
    const ull* o2t_u = (const ull*)o2t_s;
#pragma unroll 4
    for (int c = 0; c < 64; c++) {
        ull oc2 = o2t_u[c * 33 + tt];                  // coalesced LDS.64
        const ull* wol = (const ull*)(wo_s + c * 66 + c0);
        fma2(fin2[0], oc2, wol[0]);
        fma2(fin2[1], oc2, wol[1]);
    }
    int b = n0 >> 12;
    int s = (n0 & 4095) + tt;
#pragma unroll
    for (int j = 0; j < 2; j++) {
        float f0, f1;
        unpack2(fin2[j], f0, f1);
        int ch = c0 + 2 * j;
        f0 += bo[ch]     + t_s[tt * 65 + ch];
        f1 += bo[ch + 1] + t_s[tt * 65 + ch + 1];
        out[(b * 64 + ch    ) * 4096 + s] = f0;
        out[(b * 64 + ch + 1) * 4096 + s] = f1;
    }
}

// ---------------- launch ----------------
extern "C" void kernel_launch(void* const* d_in, const int* in_sizes, int n_in,
                              void* d_out, int out_size) {
    const float* x  = (const float*)d_in[0];
    const float* w1 = (const float*)d_in[1];
    const float* b1 = (const float*)d_in[2];
    const float* w2 = (const float*)d_in[3];
    const float* b2 = (const float*)d_in[4];
    const float* wq = (const float*)d_in[5];
    const float* wk = (const float*)d_in[6];
    const float* wv = (const float*)d_in[7];
    const float* wo = (const float*)d_in[8];
    const float* bo = (const float*)d_in[9];
    float* out = (float*)d_out;

    cudaFuncSetAttribute(k_attn, cudaFuncAttributeMaxDynamicSharedMemorySize,
                         SMEM_FLOATS * (int)sizeof(float));

    k_transpose_w<<<(2 * 36864 + 255) / 256, 256>>>(w1, w2);
    k_conv<0><<<dim3(1, 32, 8), dim3(512)>>>(x, b1);
    k_conv<1><<<dim3(1, 32, 8), dim3(512)>>>(x, b1);
    k_attn<<<256, 512, SMEM_FLOATS * (int)sizeof(float)>>>(wq, wk, wv, wo, bo, b2, out);
}